// round 8
// baseline (speedup 1.0000x reference)
#include <cuda_runtime.h>
#include <math.h>
#include <cstdint>

#define NN 2048
#define TT 4096
#define MAX_SPIKES 256
#define ALPHA 0.01f
#define DT (1.0f/4096.0f)
#define CLUSTER 8
#define TPB 256   // 1 neuron per thread; 8 CTAs x 256 = 2048

// Output layout (floats), tuple order: ys, tevents, yevents, event_types, num_spikes
#define YS_LEN   ((size_t)TT * NN * 3)            // 25165824
#define TEV_OFF  (YS_LEN)                         // 25165824
#define YEV_OFF  (TEV_OFF + MAX_SPIKES)           // 25166080
#define YEV_LEN  ((size_t)MAX_SPIKES * NN * 3)    // 1572864
#define ET_OFF   (YEV_OFF + YEV_LEN)              // 26738944
#define ET_LEN   ((size_t)MAX_SPIKES * NN)        // 524288
#define NS_OFF   (ET_OFF + ET_LEN)                // 27263232

__global__ void init_tail_kernel(float* __restrict__ out) {
    const float INF = __int_as_float(0x7f800000);
    size_t total = (size_t)MAX_SPIKES + YEV_LEN + ET_LEN;
    size_t stride = (size_t)gridDim.x * blockDim.x;
    for (size_t i = (size_t)blockIdx.x * blockDim.x + threadIdx.x; i < total; i += stride) {
        out[TEV_OFF + i] = (i < (size_t)MAX_SPIKES + YEV_LEN) ? INF : 0.0f;
    }
}

__device__ __forceinline__ float softplus_f(float v) {
    // jnp.logaddexp(v, 0) = max(v,0) + log1p(exp(-|v|))  (libdevice expf/log1pf)
    return __fadd_rn(fmaxf(v, 0.0f), log1pf(expf(-fabsf(v))));
}

__device__ __forceinline__ uint32_t smem_u32(const void* p) {
    uint32_t a;
    asm("{ .reg .u64 t; cvta.to.shared.u64 t, %1; cvt.u32.u64 %0, t; }" : "=r"(a) : "l"(p));
    return a;
}

__device__ __forceinline__ uint32_t ctarank() {
    uint32_t r; asm("mov.u32 %0, %%cluster_ctarank;" : "=r"(r)); return r;
}

__device__ __forceinline__ uint32_t mapa_u32(uint32_t local_addr, uint32_t rank) {
    uint32_t ra;
    asm("mapa.shared::cluster.u32 %0, %1, %2;" : "=r"(ra) : "r"(local_addr), "r"(rank));
    return ra;
}

__device__ __forceinline__ void red_min_remote(uint32_t remote_addr, int v) {
    asm volatile("red.relaxed.cluster.shared::cluster.min.s32 [%0], %1;"
                 :: "r"(remote_addr), "r"(v) : "memory");
}

__device__ __forceinline__ void mbar_arrive_remote(uint32_t remote_addr) {
    asm volatile("mbarrier.arrive.release.cluster.shared::cluster.b64 _, [%0];"
                 :: "r"(remote_addr) : "memory");
}

// wait on LOCAL mbarrier, acquire at cluster scope (makes peer reds visible)
__device__ __forceinline__ void mbar_wait_cluster(uint32_t mbar, uint32_t parity) {
    uint32_t done;
    asm volatile(
        "{\n\t"
        ".reg .pred p;\n\t"
        "mbarrier.try_wait.parity.acquire.cluster.shared::cta.b64 p, [%1], %2;\n\t"
        "selp.b32 %0, 1, 0, p;\n\t"
        "}" : "=r"(done) : "r"(mbar), "r"(parity) : "memory");
    if (!done) {
        asm volatile(
            "{\n\t"
            ".reg .pred P1;\n\t"
            "W_%=:\n\t"
            "mbarrier.try_wait.parity.acquire.cluster.shared::cta.b64 P1, [%0], %1, 0x989680;\n\t"
            "@P1 bra.uni D_%=;\n\t"
            "bra.uni W_%=;\n\t"
            "D_%=:\n\t"
            "}" :: "r"(mbar), "r"(parity) : "memory");
    }
}

#define CLUSTER_SYNC() do { \
    asm volatile("barrier.cluster.arrive.aligned;" ::: "memory"); \
    asm volatile("barrier.cluster.wait.aligned;" ::: "memory"); \
} while (0)

__global__ void __launch_bounds__(TPB, 1) __cluster_dims__(CLUSTER, 1, 1)
snn_kernel(const float* __restrict__ w,
           const float* __restrict__ mu,
           const float* __restrict__ v0,
           const float* __restrict__ i0,
           const float* __restrict__ ic,
           const float* __restrict__ u_rs,
           const float* __restrict__ u_init,
           float* __restrict__ out) {
    __shared__ int eidx[3];
    __shared__ alignas(8) unsigned long long mbar;
    const int tid  = threadIdx.x;
    const int lane = tid & 31;
    const uint32_t rank = ctarank();
    const int n = (int)rank * TPB + tid;           // this thread's neuron
    const uint32_t eidx_base = smem_u32(eidx);
    const uint32_t mbar_addr = smem_u32(&mbar);

    if (tid < 3) eidx[tid] = NN;
    if (tid == 0) {
        asm volatile("mbarrier.init.shared.b64 [%0], %1;" :: "r"(mbar_addr), "r"(CLUSTER) : "memory");
    }

    const float mu1 = mu[0], mu2 = mu[1];
    float v_  = v0[n];
    float ii  = i0[n];
    float s_  = __fsub_rn(logf(u_init[n]), ALPHA);
    int cnt = 0;

    // depth-2 prefetch of ic/u rows
    float icv = ic[n],        uvv = u_rs[n];
    float icA = ic[NN + n],   uA  = u_rs[NN + n];

    __syncthreads();
    CLUSTER_SYNC();   // all CTAs' eidx slots + mbarriers initialized before use

    int b = 0;
    for (int t = 0; t < TT; ++t) {
        // ---- 1. serial chain: softplus -> s1 -> mask -> local argmin
        float sp  = softplus_f(v_);
        float s1  = __fadd_rn(s_, __fmul_rn(DT, sp));
        bool  m   = (s1 >= 0.0f);

        unsigned val  = m ? (unsigned)n : (unsigned)NN;
        unsigned wmin = __reduce_min_sync(0xffffffffu, val);
        if (lane == 0 && wmin < NN) atomicMin(&eidx[b], (int)wmin);

        __syncthreads();

        // ---- 2. tid0: push CTA-min to all peers, then arrive on all mbarriers
        if (tid == 0) {
            int lmin = eidx[b];
            if (lmin < NN) {
                #pragma unroll
                for (uint32_t r = 0; r < CLUSTER; ++r)
                    if (r != rank) red_min_remote(mapa_u32(eidx_base + 4u * b, r), lmin);
            }
            #pragma unroll
            for (uint32_t r = 0; r < CLUSTER; ++r)
                mbar_arrive_remote(mapa_u32(mbar_addr, r));
            int b2 = b + 2; if (b2 >= 3) b2 -= 3;
            eidx[b2] = NN;   // reset slot for step t+2 (>=2 phases from its writers/readers)
        }

        // ---- 3. off-chain work hidden inside the barrier window
        if (t > 0) {
            float* yrow = out + (size_t)(t - 1) * (NN * 3) + 3 * (size_t)n;
            __stcs(yrow,     v_);
            __stcs(yrow + 1, ii);
            __stcs(yrow + 2, s_);
        }
        float v1 = __fadd_rn(v_, __fmul_rn(DT, __fmul_rn(mu1, __fsub_rn(__fadd_rn(ii, icv), v_))));
        float i1 = __fadd_rn(ii, __fmul_rn(DT, __fmul_rn(-mu2, ii)));

        float icB = 0.0f, uB = 1.0f;
        if (t + 2 < TT) {
            icB = ic  [(size_t)(t + 2) * NN + n];
            uB  = u_rs[(size_t)(t + 2) * NN + n];
        }

        // ---- 4. wait for all 8 CTAs' arrivals (phase parity = t&1)
        mbar_wait_cluster(mbar_addr, (uint32_t)(t & 1));

        int e = eidx[b];          // global argmin (first masked neuron)
        bool event = (e < NN);

        // ---- 5. transition + commit (w row applied to ALL neurons on event)
        float wn = 0.0f;
        if (event) wn = w[(size_t)e * NN + n];

        float v2 = __fsub_rn(v1, m ? 1.0f : 0.0f);
        float i2 = __fadd_rn(i1, wn);
        float s2 = m ? __fsub_rn(logf(uvv), ALPHA) : s1;

        // ---- 6. record event (first MAX_SPIKES event-steps)
        if (event && cnt < MAX_SPIKES) {
            if (rank == 0 && tid == 0)
                out[TEV_OFF + cnt] = __fmul_rn((float)t + 1.0f, DT);
            float* ye = out + YEV_OFF + (size_t)cnt * (NN * 3) + 3 * (size_t)n;
            __stcs(ye,     v1);
            __stcs(ye + 1, i1);
            __stcs(ye + 2, s1);
            __stcs(out + ET_OFF + (size_t)cnt * NN + n, m ? 1.0f : 0.0f);
            cnt++;
        }

        v_ = v2; ii = i2; s_ = s2;
        icv = icA; icA = icB;
        uvv = uA;  uA  = uB;
        b = (b == 2) ? 0 : b + 1;
    }

    // final ys row (y_new of step T-1)
    {
        float* yrow = out + (size_t)(TT - 1) * (NN * 3) + 3 * (size_t)n;
        __stcs(yrow,     v_);
        __stcs(yrow + 1, ii);
        __stcs(yrow + 2, s_);
    }
    if (rank == 0 && tid == 0) out[NS_OFF] = (float)cnt;

    // safe exit: passing the final wait means all peers' reds/arrives to this CTA landed,
    // but keep a cluster sync so no CTA tears down SMEM while a straggler still maps it.
    CLUSTER_SYNC();
}

extern "C" void kernel_launch(void* const* d_in, const int* in_sizes, int n_in,
                              void* d_out, int out_size) {
    // metadata order: w, mu, v0, i0, ic, u_init, u_resample
    const float* w      = (const float*)d_in[0];
    const float* mu     = (const float*)d_in[1];
    const float* v0     = (const float*)d_in[2];
    const float* i0     = (const float*)d_in[3];
    const float* ic     = (const float*)d_in[4];
    const float* u_init = (const float*)d_in[5];
    const float* u_rs   = (const float*)d_in[6];
    float* out = (float*)d_out;

    init_tail_kernel<<<512, 256>>>(out);
    snn_kernel<<<CLUSTER, TPB>>>(w, mu, v0, i0, ic, u_rs, u_init, out);
}

// round 11
// speedup vs baseline: 2.3872x; 2.3872x over previous
#include <cuda_runtime.h>
#include <math.h>
#include <cstdint>

#define NN 2048
#define TT 4096
#define MAX_SPIKES 256
#define ALPHA 0.01f
#define DT (1.0f/4096.0f)
#define CLUSTER 8
#define TPB 256   // 1 neuron per thread; 8 CTAs x 256 = 2048

// Output layout (floats), tuple order: ys, tevents, yevents, event_types, num_spikes
#define YS_LEN   ((size_t)TT * NN * 3)            // 25165824
#define TEV_OFF  (YS_LEN)                         // 25165824
#define YEV_OFF  (TEV_OFF + MAX_SPIKES)           // 25166080
#define YEV_LEN  ((size_t)MAX_SPIKES * NN * 3)    // 1572864
#define ET_OFF   (YEV_OFF + YEV_LEN)              // 26738944
#define ET_LEN   ((size_t)MAX_SPIKES * NN)        // 524288
#define NS_OFF   (ET_OFF + ET_LEN)                // 27263232

__global__ void init_tail_kernel(float* __restrict__ out) {
    const float INF = __int_as_float(0x7f800000);
    size_t total = (size_t)MAX_SPIKES + YEV_LEN + ET_LEN;
    size_t stride = (size_t)gridDim.x * blockDim.x;
    for (size_t i = (size_t)blockIdx.x * blockDim.x + threadIdx.x; i < total; i += stride) {
        out[TEV_OFF + i] = (i < (size_t)MAX_SPIKES + YEV_LEN) ? INF : 0.0f;
    }
}

__device__ __forceinline__ float softplus_f(float v) {
    // jnp.logaddexp(v, 0) = max(v,0) + log1p(exp(-|v|))  (libdevice expf/log1pf)
    return __fadd_rn(fmaxf(v, 0.0f), log1pf(expf(-fabsf(v))));
}

__device__ __forceinline__ uint32_t smem_u32(const void* p) {
    uint32_t a;
    asm("{ .reg .u64 t; cvta.to.shared.u64 t, %1; cvt.u32.u64 %0, t; }" : "=r"(a) : "l"(p));
    return a;
}

__device__ __forceinline__ uint32_t ctarank() {
    uint32_t r; asm("mov.u32 %0, %%cluster_ctarank;" : "=r"(r)); return r;
}

__device__ __forceinline__ void red_min_remote(uint32_t local_addr, uint32_t rank, int v) {
    uint32_t ra;
    asm volatile("mapa.shared::cluster.u32 %0, %1, %2;" : "=r"(ra) : "r"(local_addr), "r"(rank));
    asm volatile("red.relaxed.cluster.shared::cluster.min.s32 [%0], %1;" :: "r"(ra), "r"(v) : "memory");
}

#define CLUSTER_ARRIVE() asm volatile("barrier.cluster.arrive.aligned;" ::: "memory")
#define CLUSTER_WAIT()   asm volatile("barrier.cluster.wait.aligned;"   ::: "memory")

__global__ void __launch_bounds__(TPB, 1) __cluster_dims__(CLUSTER, 1, 1)
snn_kernel(const float* __restrict__ w,
           const float* __restrict__ mu,
           const float* __restrict__ v0,
           const float* __restrict__ i0,
           const float* __restrict__ ic,
           const float* __restrict__ u_rs,
           const float* __restrict__ u_init,
           float* __restrict__ out) {
    __shared__ int eidx[3];
    const int tid  = threadIdx.x;
    const int lane = tid & 31;
    const uint32_t rank = ctarank();
    const int n = (int)rank * TPB + tid;           // this thread's neuron
    const uint32_t eidx_base = smem_u32(eidx);

    if (tid < 3) eidx[tid] = NN;

    const float mu1 = mu[0], mu2 = mu[1];
    float v_  = v0[n];                              // v2(t-1)
    float ii  = i0[n];                              // i2(t-1), finalized
    float s_  = __fsub_rn(logf(u_init[n]), ALPHA);  // s2(t-1)
    float sp  = softplus_f(v_);                     // softplus(v2(t-1)), precomputed
    int cnt = 0;

    // depth-2 prefetch of ic/u rows
    float icv = ic[n],        uvv = u_rs[n];
    float icA = ic[NN + n],   uA  = u_rs[NN + n];

    __syncthreads();
    CLUSTER_ARRIVE(); CLUSTER_WAIT();   // all eidx slots initialized before remote reds

    int b = 0;
    for (int t = 0; t < TT; ++t) {
        // ---- 1. chain head: s1/mask (softplus already precomputed last window)
        float s1 = __fadd_rn(s_, __fmul_rn(DT, sp));
        bool  m  = (s1 >= 0.0f);

        unsigned val  = m ? (unsigned)n : (unsigned)NN;
        unsigned wmin = __reduce_min_sync(0xffffffffu, val);
        if (lane == 0 && wmin < NN) atomicMin(&eidx[b], (int)wmin);

        __syncthreads();

        // ---- 2. tid0: push CTA-min to peers; reset future slot
        if (tid == 0) {
            int lmin = eidx[b];
            if (lmin < NN) {
                #pragma unroll
                for (uint32_t r = 0; r < CLUSTER; ++r)
                    if (r != rank) red_min_remote(eidx_base + 4u * b, r, lmin);
            }
            int b2 = b + 2; if (b2 >= 3) b2 -= 3;
            eidx[b2] = NN;   // for step t+2; >=2 barrier phases from its writers/readers
        }

        // ---- 3. arrive, then hide ALL off-chain work in the barrier window
        CLUSTER_ARRIVE();

        // ys store of step t-1 (regs hold its committed y_new)
        if (t > 0) {
            float* yrow = out + (size_t)(t - 1) * (NN * 3) + 3 * (size_t)n;
            __stcs(yrow,     v_);
            __stcs(yrow + 1, ii);
            __stcs(yrow + 2, s_);
        }
        // v/i updates (exact reference op order); v2/s2 depend only on LOCAL mask
        float v1 = __fadd_rn(v_, __fmul_rn(DT, __fmul_rn(mu1, __fsub_rn(__fadd_rn(ii, icv), v_))));
        float i1 = __fadd_rn(ii, __fmul_rn(DT, __fmul_rn(-mu2, ii)));
        float v2 = __fsub_rn(v1, m ? 1.0f : 0.0f);
        float s2 = m ? __fsub_rn(logf(uvv), ALPHA) : s1;
        float sp_next = softplus_f(v2);             // next step's chain head input

        // prefetch ic/u for step t+2
        float icB = 0.0f, uB = 1.0f;
        if (t + 2 < TT) {
            icB = ic  [(size_t)(t + 2) * NN + n];
            uB  = u_rs[(size_t)(t + 2) * NN + n];
        }

        // ---- 4. wait: only i2 + event recording remain
        CLUSTER_WAIT();

        int e = eidx[b];          // global argmin (first masked neuron)
        bool event = (e < NN);

        float wn = 0.0f;
        if (event) wn = w[(size_t)e * NN + n];      // consumer is next window's v1
        float i2 = __fadd_rn(i1, wn);

        // ---- 5. record event (first MAX_SPIKES event-steps)
        if (event && cnt < MAX_SPIKES) {
            if (rank == 0 && tid == 0)
                out[TEV_OFF + cnt] = __fmul_rn((float)t + 1.0f, DT);
            float* ye = out + YEV_OFF + (size_t)cnt * (NN * 3) + 3 * (size_t)n;
            __stcs(ye,     v1);
            __stcs(ye + 1, i1);
            __stcs(ye + 2, s1);
            __stcs(out + ET_OFF + (size_t)cnt * NN + n, m ? 1.0f : 0.0f);
            cnt++;
        }

        // ---- 6. commit
        v_ = v2; ii = i2; s_ = s2; sp = sp_next;
        icv = icA; icA = icB;
        uvv = uA;  uA  = uB;
        b = (b == 2) ? 0 : b + 1;
    }

    // final ys row (y_new of step T-1)
    {
        float* yrow = out + (size_t)(TT - 1) * (NN * 3) + 3 * (size_t)n;
        __stcs(yrow,     v_);
        __stcs(yrow + 1, ii);
        __stcs(yrow + 2, s_);
    }
    if (rank == 0 && tid == 0) out[NS_OFF] = (float)cnt;

    // no CTA exits while peers' reds may still target its SMEM
    CLUSTER_ARRIVE(); CLUSTER_WAIT();
}

extern "C" void kernel_launch(void* const* d_in, const int* in_sizes, int n_in,
                              void* d_out, int out_size) {
    // metadata order: w, mu, v0, i0, ic, u_init, u_resample
    const float* w      = (const float*)d_in[0];
    const float* mu     = (const float*)d_in[1];
    const float* v0     = (const float*)d_in[2];
    const float* i0     = (const float*)d_in[3];
    const float* ic     = (const float*)d_in[4];
    const float* u_init = (const float*)d_in[5];
    const float* u_rs   = (const float*)d_in[6];
    float* out = (float*)d_out;

    init_tail_kernel<<<512, 256>>>(out);
    snn_kernel<<<CLUSTER, TPB>>>(w, mu, v0, i0, ic, u_rs, u_init, out);
}

// round 13
// speedup vs baseline: 3.0550x; 1.2798x over previous
#include <cuda_runtime.h>
#include <math.h>
#include <cstdint>

#define NN 2048
#define TT 4096
#define MAX_SPIKES 256
#define ALPHA 0.01f
#define DT (1.0f/4096.0f)
#define CLUSTER 8
#define TPB 256   // 1 neuron per thread; 8 CTAs x 256 = 2048
#define SLOTS 4

// Output layout (floats), tuple order: ys, tevents, yevents, event_types, num_spikes
#define YS_LEN   ((size_t)TT * NN * 3)            // 25165824
#define TEV_OFF  (YS_LEN)                         // 25165824
#define YEV_OFF  (TEV_OFF + MAX_SPIKES)           // 25166080
#define YEV_LEN  ((size_t)MAX_SPIKES * NN * 3)    // 1572864
#define ET_OFF   (YEV_OFF + YEV_LEN)              // 26738944
#define ET_LEN   ((size_t)MAX_SPIKES * NN)        // 524288
#define NS_OFF   (ET_OFF + ET_LEN)                // 27263232

__global__ void init_tail_kernel(float* __restrict__ out) {
    const float INF = __int_as_float(0x7f800000);
    size_t total = (size_t)MAX_SPIKES + YEV_LEN + ET_LEN;
    size_t stride = (size_t)gridDim.x * blockDim.x;
    for (size_t i = (size_t)blockIdx.x * blockDim.x + threadIdx.x; i < total; i += stride) {
        out[TEV_OFF + i] = (i < (size_t)MAX_SPIKES + YEV_LEN) ? INF : 0.0f;
    }
}

__device__ __forceinline__ float softplus_f(float v) {
    // jnp.logaddexp(v, 0) = max(v,0) + log1p(exp(-|v|))  (libdevice expf/log1pf)
    return __fadd_rn(fmaxf(v, 0.0f), log1pf(expf(-fabsf(v))));
}

__device__ __forceinline__ uint32_t smem_u32(const void* p) {
    uint32_t a;
    asm("{ .reg .u64 t; cvta.to.shared.u64 t, %1; cvt.u32.u64 %0, t; }" : "=r"(a) : "l"(p));
    return a;
}

__device__ __forceinline__ uint32_t ctarank() {
    uint32_t r; asm("mov.u32 %0, %%cluster_ctarank;" : "=r"(r)); return r;
}

__device__ __forceinline__ uint32_t mapa_u32(uint32_t local_addr, uint32_t rank) {
    uint32_t ra;
    asm("mapa.shared::cluster.u32 %0, %1, %2;" : "=r"(ra) : "r"(local_addr), "r"(rank));
    return ra;
}

__device__ __forceinline__ void st_remote(uint32_t remote_addr, int v) {
    asm volatile("st.relaxed.cluster.shared::cluster.b32 [%0], %1;"
                 :: "r"(remote_addr), "r"(v) : "memory");
}

#define CLUSTER_SYNC() do { \
    asm volatile("barrier.cluster.arrive.aligned;" ::: "memory"); \
    asm volatile("barrier.cluster.wait.aligned;" ::: "memory"); \
} while (0)

__global__ void __launch_bounds__(TPB, 1) __cluster_dims__(CLUSTER, 1, 1)
snn_kernel(const float* __restrict__ w,
           const float* __restrict__ mu,
           const float* __restrict__ v0,
           const float* __restrict__ i0,
           const float* __restrict__ ic,
           const float* __restrict__ u_rs,
           const float* __restrict__ u_init,
           float* __restrict__ out) {
    __shared__ int eidx[3];                 // local CTA-min accumulators (rotating)
    __shared__ int box[SLOTS][CLUSTER];     // mailbox: tag-stamped CTA-min words from all CTAs
    const int tid  = threadIdx.x;
    const int lane = tid & 31;
    const uint32_t rank = ctarank();
    const int n = (int)rank * TPB + tid;    // this thread's neuron
    const uint32_t box_base = smem_u32(box);

    if (tid < 3) eidx[tid] = NN;
    if (tid < SLOTS * CLUSTER) ((int*)box)[tid] = 0;   // tag 0 matches no step

    const float mu1 = mu[0], mu2 = mu[1];
    // state registers (committed values of step t-1 at top of step t)
    float vA  = v0[n];                               // v2(t-1)
    float sA  = __fsub_rn(logf(u_init[n]), ALPHA);   // s2(t-1)
    float spv = softplus_f(vA);                      // softplus(v2(t-1))
    float i1p = 0.0f, v1p = 0.0f, s1p = 0.0f;        // pre-transition values of t-1
    bool  mp  = false;
    const float ii0 = i0[n];
    int cnt = 0;

    // depth-2 prefetch of ic/u rows
    float icv = ic[n],        uvv = u_rs[n];
    float icA = ic[NN + n],   uA  = u_rs[NN + n];

    __syncthreads();
    CLUSTER_SYNC();   // all CTAs' eidx + box initialized before any remote traffic

    int b = 0;        // t % 3
    for (int t = 0; t < TT; ++t) {
        // ---- A. poll previous step's reduction; issue w-row load ASAP
        int e = NN;
        float wn = 0.0f;
        if (t > 0) {
            const volatile int* bx = &box[(t - 1) & 3][0];
            int a0, a1, a2, a3, a4, a5, a6, a7;
            for (;;) {
                a0 = bx[0]; a1 = bx[1]; a2 = bx[2]; a3 = bx[3];
                a4 = bx[4]; a5 = bx[5]; a6 = bx[6]; a7 = bx[7];
                int c = (a0 >> 12) ^ t; c |= (a1 >> 12) ^ t; c |= (a2 >> 12) ^ t;
                c |= (a3 >> 12) ^ t;    c |= (a4 >> 12) ^ t; c |= (a5 >> 12) ^ t;
                c |= (a6 >> 12) ^ t;    c |= (a7 >> 12) ^ t;
                if (c == 0) break;
            }
            int m01 = min(a0 & 0xFFF, a1 & 0xFFF);
            int m23 = min(a2 & 0xFFF, a3 & 0xFFF);
            int m45 = min(a4 & 0xFFF, a5 & 0xFFF);
            int m67 = min(a6 & 0xFFF, a7 & 0xFFF);
            e = min(min(m01, m23), min(m45, m67));
            if (e < NN) wn = w[(size_t)e * NN + n];   // overlaps mask chain below
        }

        // ---- B. mask chain for step t
        float s1 = __fadd_rn(sA, __fmul_rn(DT, spv));
        bool  m  = (s1 >= 0.0f);
        unsigned val  = m ? (unsigned)n : (unsigned)NN;
        unsigned wmin = __reduce_min_sync(0xffffffffu, val);
        if (lane == 0 && wmin < NN) atomicMin(&eidx[b], (int)wmin);

        __syncthreads();

        // ---- C. publish step-t CTA-min to all CTAs (tag = t+1); reset slot for t+2
        if (tid == 0) {
            int wordv = ((t + 1) << 12) | eidx[b];
            uint32_t off = box_base + 4u * ((uint32_t)(t & 3) * CLUSTER + rank);
            #pragma unroll
            for (uint32_t r = 0; r < CLUSTER; ++r)
                st_remote(mapa_u32(off, r), wordv);
            int b2 = b + 2; if (b2 >= 3) b2 -= 3;
            eidx[b2] = NN;   // writers of this slot are 2 __syncthreads away
        }

        // ---- D. finalize step t-1: i2, event record, ys row
        float i2p;
        if (t > 0) {
            i2p = __fadd_rn(i1p, wn);
            if (e < NN && cnt < MAX_SPIKES) {
                if (rank == 0 && tid == 0)
                    out[TEV_OFF + cnt] = __fmul_rn((float)t, DT);
                float* ye = out + YEV_OFF + (size_t)cnt * (NN * 3) + 3 * (size_t)n;
                __stcs(ye,     v1p);
                __stcs(ye + 1, i1p);
                __stcs(ye + 2, s1p);
                __stcs(out + ET_OFF + (size_t)cnt * NN + n, mp ? 1.0f : 0.0f);
                cnt++;
            }
            float* yrow = out + (size_t)(t - 1) * (NN * 3) + 3 * (size_t)n;
            __stcs(yrow,     vA);
            __stcs(yrow + 1, i2p);
            __stcs(yrow + 2, sA);
        } else {
            i2p = ii0;
        }

        // ---- E. advance step t (exact reference op order)
        float v1 = __fadd_rn(vA, __fmul_rn(DT, __fmul_rn(mu1, __fsub_rn(__fadd_rn(i2p, icv), vA))));
        float i1 = __fadd_rn(i2p, __fmul_rn(DT, __fmul_rn(-mu2, i2p)));
        float v2 = __fsub_rn(v1, m ? 1.0f : 0.0f);
        float s2 = m ? __fsub_rn(logf(uvv), ALPHA) : s1;
        float spn = softplus_f(v2);

        // ---- F. prefetch ic/u for t+2; commit
        float icB = 0.0f, uB = 1.0f;
        if (t + 2 < TT) {
            icB = ic  [(size_t)(t + 2) * NN + n];
            uB  = u_rs[(size_t)(t + 2) * NN + n];
        }

        vA = v2; sA = s2; spv = spn;
        i1p = i1; v1p = v1; s1p = s1; mp = m;
        icv = icA; icA = icB;
        uvv = uA;  uA  = uB;
        b = (b == 2) ? 0 : b + 1;
    }

    // ---- epilogue: finalize step TT-1
    {
        const volatile int* bx = &box[(TT - 1) & 3][0];
        int a0, a1, a2, a3, a4, a5, a6, a7;
        for (;;) {
            a0 = bx[0]; a1 = bx[1]; a2 = bx[2]; a3 = bx[3];
            a4 = bx[4]; a5 = bx[5]; a6 = bx[6]; a7 = bx[7];
            int c = (a0 >> 12) ^ TT; c |= (a1 >> 12) ^ TT; c |= (a2 >> 12) ^ TT;
            c |= (a3 >> 12) ^ TT;    c |= (a4 >> 12) ^ TT; c |= (a5 >> 12) ^ TT;
            c |= (a6 >> 12) ^ TT;    c |= (a7 >> 12) ^ TT;
            if (c == 0) break;
        }
        int e = min(min(min(a0 & 0xFFF, a1 & 0xFFF), min(a2 & 0xFFF, a3 & 0xFFF)),
                    min(min(a4 & 0xFFF, a5 & 0xFFF), min(a6 & 0xFFF, a7 & 0xFFF)));
        float wn = 0.0f;
        if (e < NN) wn = w[(size_t)e * NN + n];
        float i2p = __fadd_rn(i1p, wn);
        if (e < NN && cnt < MAX_SPIKES) {
            if (rank == 0 && tid == 0)
                out[TEV_OFF + cnt] = __fmul_rn((float)TT, DT);
            float* ye = out + YEV_OFF + (size_t)cnt * (NN * 3) + 3 * (size_t)n;
            __stcs(ye,     v1p);
            __stcs(ye + 1, i1p);
            __stcs(ye + 2, s1p);
            __stcs(out + ET_OFF + (size_t)cnt * NN + n, mp ? 1.0f : 0.0f);
            cnt++;
        }
        float* yrow = out + (size_t)(TT - 1) * (NN * 3) + 3 * (size_t)n;
        __stcs(yrow,     vA);
        __stcs(yrow + 1, i2p);
        __stcs(yrow + 2, sA);
    }
    if (rank == 0 && tid == 0) out[NS_OFF] = (float)cnt;

    // no CTA exits while peers' mailbox stores may still target its SMEM
    CLUSTER_SYNC();
}

extern "C" void kernel_launch(void* const* d_in, const int* in_sizes, int n_in,
                              void* d_out, int out_size) {
    // metadata order: w, mu, v0, i0, ic, u_init, u_resample
    const float* w      = (const float*)d_in[0];
    const float* mu     = (const float*)d_in[1];
    const float* v0     = (const float*)d_in[2];
    const float* i0     = (const float*)d_in[3];
    const float* ic     = (const float*)d_in[4];
    const float* u_init = (const float*)d_in[5];
    const float* u_rs   = (const float*)d_in[6];
    float* out = (float*)d_out;

    init_tail_kernel<<<512, 256>>>(out);
    snn_kernel<<<CLUSTER, TPB>>>(w, mu, v0, i0, ic, u_rs, u_init, out);
}